// round 2
// baseline (speedup 1.0000x reference)
#include <cuda_runtime.h>

#define D_IN 8
#define HID 64
#define EPS 1e-5f

// LayerNorm (two-pass) + tanh over a 64-float register array.
__device__ __forceinline__ void ln_tanh64(float* __restrict__ h,
                                          const float* __restrict__ g,
                                          const float* __restrict__ be) {
    float s = 0.f;
#pragma unroll
    for (int i = 0; i < HID; i++) s += h[i];
    float m = s * (1.0f / HID);
    float ss = 0.f;
#pragma unroll
    for (int i = 0; i < HID; i++) { float d = h[i] - m; ss = fmaf(d, d, ss); }
    float inv = rsqrtf(ss * (1.0f / HID) + EPS);
#pragma unroll
    for (int i = 0; i < HID; i++) {
        h[i] = tanhf(fmaf((h[i] - m) * inv, g[i], be[i]));
    }
}

__global__ __launch_bounds__(128) void edge_mlp_kernel(
    const float* __restrict__ x,
    const int* __restrict__ ei,
    const float* __restrict__ W0, const float* __restrict__ b0,
    const float* __restrict__ g0, const float* __restrict__ be0,
    const float* __restrict__ W1, const float* __restrict__ b1,
    const float* __restrict__ g1, const float* __restrict__ be1,
    const float* __restrict__ W2, const float* __restrict__ b2,
    const float* __restrict__ g2, const float* __restrict__ be2,
    const float* __restrict__ W3, const float* __restrict__ b3,
    float* __restrict__ out, int n_edges)
{
    __shared__ __align__(16) float sW0[2 * D_IN * HID];   // 16x64
    __shared__ __align__(16) float sW1[HID * HID];        // 64x64
    __shared__ __align__(16) float sW2[HID * HID];        // 64x64
    __shared__ __align__(16) float sW3[HID];
    __shared__ __align__(16) float sb0[HID], sb1[HID], sb2[HID];
    __shared__ __align__(16) float sg0[HID], sbe0[HID];
    __shared__ __align__(16) float sg1[HID], sbe1[HID];
    __shared__ __align__(16) float sg2[HID], sbe2[HID];
    __shared__ float sb3;

    const int t = threadIdx.x;
    for (int i = t; i < 2 * D_IN * HID; i += blockDim.x) sW0[i] = W0[i];
    for (int i = t; i < HID * HID; i += blockDim.x) sW1[i] = W1[i];
    for (int i = t; i < HID * HID; i += blockDim.x) sW2[i] = W2[i];
    if (t < HID) {
        sW3[t] = W3[t];
        sb0[t] = b0[t]; sb1[t] = b1[t]; sb2[t] = b2[t];
        sg0[t] = g0[t]; sbe0[t] = be0[t];
        sg1[t] = g1[t]; sbe1[t] = be1[t];
        sg2[t] = g2[t]; sbe2[t] = be2[t];
    }
    if (t == 0) sb3 = b3[0];
    __syncthreads();

    const float4* __restrict__ x4 = (const float4*)x;
    const int stride = gridDim.x * blockDim.x;

    for (int e = blockIdx.x * blockDim.x + threadIdx.x; e < n_edges; e += stride) {
        // Gather and concat: in[0..7] = x[start], in[8..15] = x[end]
        const int s = ei[e];
        const int d = ei[n_edges + e];
        float in[2 * D_IN];
        {
            float4 a0 = x4[2 * s], a1 = x4[2 * s + 1];
            float4 c0 = x4[2 * d], c1 = x4[2 * d + 1];
            in[0] = a0.x; in[1] = a0.y; in[2] = a0.z; in[3] = a0.w;
            in[4] = a1.x; in[5] = a1.y; in[6] = a1.z; in[7] = a1.w;
            in[8] = c0.x; in[9] = c0.y; in[10] = c0.z; in[11] = c0.w;
            in[12] = c1.x; in[13] = c1.y; in[14] = c1.z; in[15] = c1.w;
        }

        float hA[HID], hB[HID];

        // ---- Layer 0: [16] @ W0[16x64] + b0 ----
        for (int k = 0; k < HID; k += 4) {
            float4 acc = *(const float4*)&sb0[k];
#pragma unroll
            for (int j = 0; j < 2 * D_IN; j++) {
                float4 w = *(const float4*)&sW0[j * HID + k];
                acc.x = fmaf(in[j], w.x, acc.x);
                acc.y = fmaf(in[j], w.y, acc.y);
                acc.z = fmaf(in[j], w.z, acc.z);
                acc.w = fmaf(in[j], w.w, acc.w);
            }
            hA[k] = acc.x; hA[k + 1] = acc.y; hA[k + 2] = acc.z; hA[k + 3] = acc.w;
        }
        ln_tanh64(hA, sg0, sbe0);

        // ---- Layer 1: [64] @ W1[64x64] + b1 ----
        for (int k = 0; k < HID; k += 4) {
            float4 acc = *(const float4*)&sb1[k];
#pragma unroll
            for (int j = 0; j < HID; j++) {
                float4 w = *(const float4*)&sW1[j * HID + k];
                acc.x = fmaf(hA[j], w.x, acc.x);
                acc.y = fmaf(hA[j], w.y, acc.y);
                acc.z = fmaf(hA[j], w.z, acc.z);
                acc.w = fmaf(hA[j], w.w, acc.w);
            }
            hB[k] = acc.x; hB[k + 1] = acc.y; hB[k + 2] = acc.z; hB[k + 3] = acc.w;
        }
        ln_tanh64(hB, sg1, sbe1);

        // ---- Layer 2: [64] @ W2[64x64] + b2 ----
        for (int k = 0; k < HID; k += 4) {
            float4 acc = *(const float4*)&sb2[k];
#pragma unroll
            for (int j = 0; j < HID; j++) {
                float4 w = *(const float4*)&sW2[j * HID + k];
                acc.x = fmaf(hB[j], w.x, acc.x);
                acc.y = fmaf(hB[j], w.y, acc.y);
                acc.z = fmaf(hB[j], w.z, acc.z);
                acc.w = fmaf(hB[j], w.w, acc.w);
            }
            hA[k] = acc.x; hA[k + 1] = acc.y; hA[k + 2] = acc.z; hA[k + 3] = acc.w;
        }
        ln_tanh64(hA, sg2, sbe2);

        // ---- Layer 3: [64] @ W3[64x1] + b3 ----
        float o = sb3;
#pragma unroll
        for (int j = 0; j < HID; j++) o = fmaf(hA[j], sW3[j], o);

        out[e] = o;
    }
}

extern "C" void kernel_launch(void* const* d_in, const int* in_sizes, int n_in,
                              void* d_out, int out_size) {
    const float* x   = (const float*)d_in[0];
    const int*   ei  = (const int*)d_in[1];
    const float* W0 = (const float*)d_in[2];
    const float* b0 = (const float*)d_in[3];
    const float* g0 = (const float*)d_in[4];
    const float* be0 = (const float*)d_in[5];
    const float* W1 = (const float*)d_in[6];
    const float* b1 = (const float*)d_in[7];
    const float* g1 = (const float*)d_in[8];
    const float* be1 = (const float*)d_in[9];
    const float* W2 = (const float*)d_in[10];
    const float* b2 = (const float*)d_in[11];
    const float* g2 = (const float*)d_in[12];
    const float* be2 = (const float*)d_in[13];
    const float* W3 = (const float*)d_in[14];
    const float* b3 = (const float*)d_in[15];
    float* out = (float*)d_out;

    const int n_edges = in_sizes[1] / 2;

    const int threads = 128;
    const int blocks = 148 * 16;  // grid-stride; amortizes smem weight staging
    edge_mlp_kernel<<<blocks, threads>>>(x, ei,
                                         W0, b0, g0, be0,
                                         W1, b1, g1, be1,
                                         W2, b2, g2, be2,
                                         W3, b3, out, n_edges);
}